// round 8
// baseline (speedup 1.0000x reference)
#include <cuda_runtime.h>
#include <cuda_bf16.h>
#include <cstdint>

// N = 400 nodes, E = N*(N-1) = 159600 edges, B = 32 batch.
// Output [B, E, 2] f32: out[b,e,:] = adj[i,j]!=0 ? (0,1) : (1,0),
// edge e -> (i = e/399, j = r + (r>=i)), r = e%399  (np.where(~eye) order).
//
// The kernel is bounded by the L2/LTS WRITE ceiling (~4.3 TB/s chip-wide;
// measured invariant across STG / stcs / cp.async.bulk / dual-path variants).
// The only remaining lever is per-SM byte balance: grid = exactly 148 CTAs
// (one per SM), per-CTA chunks of 539/540 edge-pairs (max 0.2% skew), each
// thread computes its float4 ONCE and broadcasts to all 32 batch images with
// plain coalesced STG.128.

#define N_NODES 400
#define N_M1    399
#define E_PAIRS 79800           // float4 elements per batch
#define BATCH   32
#define GRID_X  148             // one CTA per SM
#define THREADS 512
#define CHUNK_LO 539            // 148*539 = 79772; remainder 28 CTAs get 540
#define REM      28

__device__ __forceinline__ float4 make_pair_val(const float* __restrict__ adj, int p)
{
    const int e0 = 2 * p;
    const int e1 = e0 + 1;
    int i0 = e0 / N_M1;
    int r0 = e0 - i0 * N_M1;
    int j0 = r0 + (r0 >= i0 ? 1 : 0);
    int i1 = e1 / N_M1;
    int r1 = e1 - i1 * N_M1;
    int j1 = r1 + (r1 >= i1 ? 1 : 0);
    const float t0 = (__ldg(&adj[i0 * N_NODES + j0]) != 0.0f) ? 1.0f : 0.0f;
    const float t1 = (__ldg(&adj[i1 * N_NODES + j1]) != 0.0f) ? 1.0f : 0.0f;
    return make_float4(1.0f - t0, t0, 1.0f - t1, t1);
}

__global__ __launch_bounds__(THREADS)
void edge_onehot_balanced_kernel(const float* __restrict__ adj, float4* __restrict__ out)
{
    const int bid = blockIdx.x;
    const int tid = threadIdx.x;

    // Per-CTA contiguous chunk: first REM CTAs take CHUNK_LO+1 pairs.
    const int cnt   = CHUNK_LO + (bid < REM ? 1 : 0);
    const int start = bid * CHUNK_LO + (bid < REM ? bid : REM);

    // Element 1: tid in [0, cnt)  (cnt = 539/540 > THREADS, so all threads active)
    {
        const int p = start + tid;
        if (tid < cnt) {
            const float4 v = make_pair_val(adj, p);
            float4* dst = out + p;
#pragma unroll
            for (int b = 0; b < BATCH; ++b)
                dst[(size_t)b * E_PAIRS] = v;
        }
    }
    // Element 2: tid + THREADS in [THREADS, cnt)  (27/28 threads)
    {
        const int idx = tid + THREADS;
        if (idx < cnt) {
            const int p = start + idx;
            const float4 v = make_pair_val(adj, p);
            float4* dst = out + p;
#pragma unroll
            for (int b = 0; b < BATCH; ++b)
                dst[(size_t)b * E_PAIRS] = v;
        }
    }
}

extern "C" void kernel_launch(void* const* d_in, const int* in_sizes, int n_in,
                              void* d_out, int out_size)
{
    // metadata order: inputs, weather, rel_rec, rel_send, adj_matrix
    const float* adj = (const float*)d_in[4];
    float4* out = (float4*)d_out;

    edge_onehot_balanced_kernel<<<GRID_X, THREADS>>>(adj, out);
}